// round 8
// baseline (speedup 1.0000x reference)
#include <cuda_runtime.h>

#define NCLS 19
#define FPX  16384      // 128*128 feature pixels
#define DCH  64
#define LBL  512
#define SCH  16         // list chunks (grid.y of mom/kde)
#define NTP  256
#define PADQ 512        // list pad quantum (multiple of 256)
#define CHPX 8192

__device__ unsigned char g_cnt8[NCLS * FPX];
__device__ unsigned int  g_pairs[NCLS * FPX];   // (w<<16)|pixel, zero-padded
__device__ int           g_len[NCLS];
__device__ float         g_n[NCLS];
__device__ float         g_ft[FPX * DCH];       // transposed feature [p][d]
__device__ float         g_m1p[NCLS * SCH * DCH];
__device__ float         g_m2p[NCLS * SCH * DCH];
__device__ float         g_binp[NCLS * SCH * DCH * 8];  // 7 bins used, pad 8
__device__ float         g_closs[NCLS];
__device__ int           g_ctick[NCLS];
__device__ int           g_gtick;

typedef unsigned long long ull;

__device__ __forceinline__ float ex2f(float x) {
    float y; asm("ex2.approx.ftz.f32 %0, %1;" : "=f"(y) : "f"(x)); return y;
}
__device__ __forceinline__ ull pk2(float lo, float hi) {
    ull r; asm("mov.b64 %0, {%1, %2};" : "=l"(r) : "f"(lo), "f"(hi)); return r;
}
__device__ __forceinline__ ull pkb(unsigned lo, unsigned hi) {
    ull r; asm("mov.b64 %0, {%1, %2};" : "=l"(r) : "r"(lo), "r"(hi)); return r;
}
__device__ __forceinline__ void upk2(float& lo, float& hi, ull v) {
    asm("mov.b64 {%0, %1}, %2;" : "=f"(lo), "=f"(hi) : "l"(v));
}
__device__ __forceinline__ ull fma2(ull a, ull b, ull c) {
    ull d; asm("fma.rn.f32x2 %0, %1, %2, %3;" : "=l"(d) : "l"(a), "l"(b), "l"(c)); return d;
}
__device__ __forceinline__ ull mul2(ull a, ull b) {
    ull d; asm("mul.rn.f32x2 %0, %1, %2;" : "=l"(d) : "l"(a), "l"(b)); return d;
}

// recurrence constants (exponent -12.5(k-t)^2 in base 2):
#define CLK  (-18.033688011112042f)    // -12.5*log2(e)
#define RA   (-36.06737602222409f)     // -25*log2(e)
#define RB   (90.16844005556021f)      //  62.5*log2(e)
#define CCM  (1.3887943864964021e-11f) // exp(-25)

// ───── K0: prep = feature transpose (blocks 0..255) + label counts (256..319)
__global__ __launch_bounds__(256) void prep_kernel(const float* __restrict__ feat,
                                                   const int* __restrict__ label) {
    __shared__ float sm[64][65];
    const int bi = blockIdx.x, tid = threadIdx.x;
    if (bi < 256) {
        const int pixbase = bi * 64;
        const int sub = tid >> 6, low = tid & 63;
#pragma unroll
        for (int it = 0; it < 16; it++) {
            int d = sub + it * 4;
            sm[d][low] = feat[d * FPX + pixbase + low];
        }
        __syncthreads();
#pragma unroll
        for (int it = 0; it < 16; it++) {
            int p_off = sub + it * 4;
            g_ft[(pixbase + p_off) * 64 + low] = sm[low][p_off];
        }
    } else {
        const int fp = (bi - 256) * 256 + tid;
        const int r = fp >> 7, c = fp & 127;
        const int4* lp = reinterpret_cast<const int4*>(label + (r * 4) * LBL + c * 4);
        unsigned pk[4];
#pragma unroll
        for (int dr = 0; dr < 4; dr++) {
            int4 v = lp[dr * (LBL / 4)];
            pk[dr] = (unsigned)v.x | ((unsigned)v.y << 8) |
                     ((unsigned)v.z << 16) | ((unsigned)v.w << 24);
        }
#pragma unroll
        for (int cls = 0; cls < NCLS; cls++) {
            unsigned u = (unsigned)cls * 0x01010101u;
            int s = 0;
#pragma unroll
            for (int dr = 0; dr < 4; dr++)
                s = __dp4a((int)(__vcmpeq4(pk[dr], u) & 0x01010101u), 0x01010101, s);
            g_cnt8[cls * FPX + fp] = (unsigned char)s;
        }
    }
}

// ───── K1: ordered compaction (one block per class)
__global__ __launch_bounds__(NTP) void compact_kernel() {
    const int cls = blockIdx.x;
    const int tid = threadIdx.x, lane = tid & 31, wid = tid >> 5;
    __shared__ unsigned sbuf[CHPX];
    __shared__ unsigned wtot[8], wbase[8];
    __shared__ int wsumw[8];
    __shared__ unsigned chtot_s;
    __shared__ int nacc_s;

    if (tid == 0) nacc_s = 0;
    unsigned gbase = 0;
    unsigned int* __restrict__ out = g_pairs + cls * FPX;

    for (int h = 0; h < FPX / CHPX; h++) {
        const int pxbase = h * CHPX + tid * 32;
        unsigned d[8];
        const uint4* src = reinterpret_cast<const uint4*>(g_cnt8 + cls * FPX + h * CHPX)
                           + tid * 2;
        uint4 v0 = src[0], v1 = src[1];
        d[0]=v0.x; d[1]=v0.y; d[2]=v0.z; d[3]=v0.w;
        d[4]=v1.x; d[5]=v1.y; d[6]=v1.z; d[7]=v1.w;

        int nnz = 0, ws = 0;
#pragma unroll
        for (int j = 0; j < 8; j++) {
            unsigned u = d[j];
            nnz += __popc(__vcmpne4(u, 0u) & 0x01010101u);
            ws  += __dp4a((int)u, 0x01010101, 0);
        }
        unsigned inc = (unsigned)nnz;
#pragma unroll
        for (int o = 1; o < 32; o <<= 1) {
            unsigned t = __shfl_up_sync(0xffffffffu, inc, o);
            if (lane >= o) inc += t;
        }
        if (lane == 31) wtot[wid] = inc;
        int wsr = ws;
#pragma unroll
        for (int o = 16; o; o >>= 1) wsr += __shfl_xor_sync(0xffffffffu, wsr, o);
        if (lane == 0) wsumw[wid] = wsr;
        __syncthreads();
        if (tid == 0) {
            unsigned run = 0; int ns = 0;
#pragma unroll
            for (int j = 0; j < 8; j++) { wbase[j] = run; run += wtot[j]; ns += wsumw[j]; }
            chtot_s = run;
            nacc_s += ns;
        }
        __syncthreads();

        unsigned rank = wbase[wid] + inc - (unsigned)nnz;
#pragma unroll
        for (int j = 0; j < 8; j++) {
            unsigned u = d[j];
#pragma unroll
            for (int b = 0; b < 4; b++) {
                unsigned w = (u >> (8 * b)) & 0xffu;
                if (w) sbuf[rank++] = (w << 16) | (unsigned)(pxbase + j * 4 + b);
            }
        }
        __syncthreads();
        unsigned chtot = chtot_s;
        for (unsigned j = tid; j < chtot; j += NTP) out[gbase + j] = sbuf[j];
        gbase += chtot;
        __syncthreads();
    }
    unsigned pl = (gbase + PADQ - 1) & ~(unsigned)(PADQ - 1);
    for (unsigned k = gbase + tid; k < pl; k += NTP) out[k] = 0u;
    if (tid == 0) { g_len[cls] = (int)pl; g_n[cls] = (float)nacc_s; }
}

// ───── K2: partial moments per (class, chunk). lane = channel-pair.
__global__ __launch_bounds__(256) void mom_kernel() {
    const int cls = blockIdx.x, s = blockIdx.y;
    if (g_n[cls] < 1000.0f) return;
    const int tid = threadIdx.x, lane = tid & 31, wid = tid >> 5;
    const int len = g_len[cls];
    const unsigned* __restrict__ pr = g_pairs + cls * FPX;
    const float2* __restrict__ ft2 = reinterpret_cast<const float2*>(g_ft);

    ull s1 = 0ull, s2 = 0ull;
    for (int e = s + SCH * wid; e < len; e += 256) {
        unsigned pa = __ldg(pr + e);
        unsigned pb = __ldg(pr + e + 128);
        float2 fa = ft2[(pa & 0xFFFFu) * 32 + lane];
        float2 fc = ft2[(pb & 0xFFFFu) * 32 + lane];
        float wa = (float)(pa >> 16), wb = (float)(pb >> 16);
        ull fa2 = pk2(fa.x, fa.y), fc2 = pk2(fc.x, fc.y);
        ull wa2 = pk2(wa, wa),     wb2 = pk2(wb, wb);
        s1 = fma2(fa2, wa2, s1);
        s2 = fma2(mul2(fa2, fa2), wa2, s2);
        s1 = fma2(fc2, wb2, s1);
        s2 = fma2(mul2(fc2, fc2), wb2, s2);
    }
    __shared__ float2 sm1[8][32], sm2[8][32];
    float l1, h1, l2, h2;
    upk2(l1, h1, s1); upk2(l2, h2, s2);
    sm1[wid][lane] = make_float2(l1, h1);
    sm2[wid][lane] = make_float2(l2, h2);
    __syncthreads();
    if (tid < 32) {
        float a = 0.f, b = 0.f, c = 0.f, d = 0.f;
#pragma unroll
        for (int w = 0; w < 8; w++) {
            a += sm1[w][tid].x; b += sm1[w][tid].y;
            c += sm2[w][tid].x; d += sm2[w][tid].y;
        }
        int base = (cls * SCH + s) * DCH + tid * 2;
        g_m1p[base] = a; g_m1p[base + 1] = b;
        g_m2p[base] = c; g_m2p[base + 1] = d;
    }
}

__device__ __forceinline__ void kde_ch(unsigned pv, float2 fv, ull invs2, ull nmu2,
                                       ull cc2, ull* accP, ull* accN) {
    float wf = (float)(pv >> 16);
    ull f2 = pk2(fv.x, fv.y);
    ull t2 = fma2(f2, invs2, nmu2);
    float t0, t1; upk2(t0, t1, t2);
    float a0 = fabsf(t0), a1 = fabsf(t1);
    float x0 = 3.0f - a0, x1 = 3.0f - a1;
    float gl = ex2f(fmaf(CLK * x0, x0, 100.0f));
    float gh = ex2f(fmaf(CLK * x1, x1, 100.0f));
    float rl = ex2f(fmaf(RA, a0, RB));
    float rh = ex2f(fmaf(RA, a1, RB));
    unsigned m0 = (unsigned)(__float_as_int(t0) >> 31);
    unsigned m1 = (unsigned)(__float_as_int(t1) >> 31);
    unsigned wb = __float_as_uint(wf);
    ull wp2 = pkb(wb & ~m0, wb & ~m1);
    ull wn2 = pkb(wb &  m0, wb &  m1);
    ull g = pk2(gl, gh), r = pk2(rl, rh);
#pragma unroll
    for (int k = 0; k < 7; k++) {
        accP[k] = fma2(wp2, g, accP[k]);
        accN[k] = fma2(wn2, g, accN[k]);
        if (k < 6) { g = mul2(g, r); r = mul2(r, cc2); }
    }
}

// ───── K3: recurrence KDE per (class, chunk); class ticket -> bins+loss;
//          global ticket -> scalar.
__global__ __launch_bounds__(256) void kde_kernel(float* __restrict__ outp) {
    const int cls = blockIdx.x, sb = blockIdx.y;
    const int tid = threadIdx.x, lane = tid & 31, wid = tid >> 5;
    const float n = g_n[cls];
    const bool active = (n >= 1000.0f);

    __shared__ float sinv[DCH], snmu[DCH];
    __shared__ float2 stgP[8][32][7], stgN[8][32][7];
    __shared__ float red[8];
    __shared__ int sflag, gflag;

    if (active) {
        if (tid < DCH) {
            float S1 = 0.f, S2 = 0.f;
#pragma unroll
            for (int s = 0; s < SCH; s++) {
                int base = (cls * SCH + s) * DCH + tid;
                S1 += g_m1p[base];
                S2 += g_m2p[base];
            }
            float nsafe = fmaxf(n, 1.0f);
            float miu = S1 / nsafe;
            float var = fmaxf(S2 / nsafe - miu * miu, 0.0f) + 1e-10f;
            float invs = rsqrtf(var);
            sinv[tid] = invs;
            snmu[tid] = -miu * invs;
        }
    }
    __syncthreads();

    if (active) {
        const int len = g_len[cls];
        const unsigned* __restrict__ pr = g_pairs + cls * FPX;
        const float2* __restrict__ ft2 = reinterpret_cast<const float2*>(g_ft);
        const ull invs2 = pk2(sinv[2 * lane], sinv[2 * lane + 1]);
        const ull nmu2  = pk2(snmu[2 * lane], snmu[2 * lane + 1]);
        const ull cc2   = pk2(CCM, CCM);
        ull accP[7], accN[7];
#pragma unroll
        for (int k = 0; k < 7; k++) { accP[k] = 0ull; accN[k] = 0ull; }

        for (int e = sb + SCH * wid; e < len; e += 256) {
            unsigned pa = __ldg(pr + e);
            unsigned pb = __ldg(pr + e + 128);
            float2 fa = ft2[(pa & 0xFFFFu) * 32 + lane];
            float2 fc = ft2[(pb & 0xFFFFu) * 32 + lane];
            kde_ch(pa, fa, invs2, nmu2, cc2, accP, accN);
            kde_ch(pb, fc, invs2, nmu2, cc2, accP, accN);
        }
#pragma unroll
        for (int k = 0; k < 7; k++) {
            float lo, hi;
            upk2(lo, hi, accP[k]); stgP[wid][lane][k] = make_float2(lo, hi);
            upk2(lo, hi, accN[k]); stgN[wid][lane][k] = make_float2(lo, hi);
        }
    }
    __syncthreads();

    if (active && tid < DCH) {
        const int pi = tid >> 1, comp = tid & 1;
        float P[7], N[7];
#pragma unroll
        for (int k = 0; k < 7; k++) {
            float vP = 0.f, vN = 0.f;
#pragma unroll
            for (int w = 0; w < 8; w++) {
                float2 p2 = stgP[w][pi][k], n2 = stgN[w][pi][k];
                vP += comp ? p2.y : p2.x;
                vN += comp ? n2.y : n2.x;
            }
            P[k] = vP; N[k] = vN;
        }
        int base = ((cls * SCH + sb) * DCH + tid) * 8;
#pragma unroll
        for (int ib = 0; ib < 7; ib++)
            g_binp[base + ib] = P[6 - ib] + N[ib];   // fold sign banks
    }
    __threadfence();
    if (tid == 0) {
        int t = atomicAdd(&g_ctick[cls], 1);
        sflag = (t == SCH - 1) ? 1 : 0;
    }
    __syncthreads();

    if (sflag) {
        __threadfence();
        float myloss = 0.f;
        if (active && tid < DCH) {
            float sbin[7], tot = 0.f;
#pragma unroll
            for (int ib = 0; ib < 7; ib++) {
                float v = 0.f;
#pragma unroll
                for (int s = 0; s < SCH; s++)
                    v += g_binp[((cls * SCH + s) * DCH + tid) * 8 + ib];
                sbin[ib] = v; tot += v;
            }
            float inv = 1.0f / fmaxf(tot, 1e-30f);
            const float targ[7] = {0.00443305f, 0.05400558f, 0.24203623f, 0.39905027f,
                                   0.24203623f, 0.05400558f, 0.00443305f};
            float L = 0.f;
#pragma unroll
            for (int ib = 0; ib < 7; ib++) {
                float dif = fabsf(sbin[ib] * inv - targ[ib]);
                L += (dif < 1.0f) ? 0.5f * dif * dif : (dif - 0.5f);
            }
            myloss = L;
        }
        float v = myloss;
#pragma unroll
        for (int o = 16; o; o >>= 1) v += __shfl_xor_sync(0xffffffffu, v, o);
        if (lane == 0) red[wid] = v;
        __syncthreads();
        if (tid == 0) {
            float sum = 0.f;
#pragma unroll
            for (int w = 0; w < 8; w++) sum += red[w];
            g_closs[cls] = active ? sum * (1.0f / (7.0f * (float)DCH)) : 0.f;
            g_ctick[cls] = 0;   // reset for next graph replay
            __threadfence();
            int gt = atomicAdd(&g_gtick, 1);
            gflag = (gt == NCLS - 1) ? 1 : 0;
        }
        __syncthreads();
        if (gflag && tid == 0) {
            __threadfence();
            float num = 0.f, den = 0.f;
#pragma unroll
            for (int c = 0; c < NCLS; c++) {
                num += g_closs[c];
                den += (g_n[c] >= 1000.0f) ? 1.0f : 0.0f;
            }
            outp[0] = num / den;
            g_gtick = 0;        // reset for next graph replay
        }
    }
}

extern "C" void kernel_launch(void* const* d_in, const int* in_sizes, int n_in,
                              void* d_out, int out_size) {
    const float* feature;
    const int*   label;
    if (in_sizes[0] == DCH * FPX) {
        feature = (const float*)d_in[0];
        label   = (const int*)d_in[1];
    } else {
        feature = (const float*)d_in[1];
        label   = (const int*)d_in[0];
    }
    prep_kernel<<<320, 256>>>(feature, label);
    compact_kernel<<<NCLS, NTP>>>();
    mom_kernel<<<dim3(NCLS, SCH), 256>>>();
    kde_kernel<<<dim3(NCLS, SCH), 256>>>((float*)d_out);
}

// round 10
// speedup vs baseline: 1.1412x; 1.1412x over previous
#include <cuda_runtime.h>

#define NCLS 19
#define FPX  16384      // 128*128 feature pixels
#define DCH  64
#define LBL  512
#define SCH  48         // list chunks (grid.y of mom/kde)
#define NTP  256
#define PADQ (SCH*16)   // list pad quantum = 768 (multiple of warp tiling)
#define CHPX 8192

__device__ unsigned char g_cnt8[NCLS * FPX];
__device__ unsigned int  g_pairs[NCLS * FPX];   // (w<<16)|pixel, zero-padded
__device__ int           g_len[NCLS];
__device__ float         g_n[NCLS];
__device__ float         g_ft[FPX * DCH];       // transposed feature [p][d]
__device__ float         g_m1p[NCLS * SCH * DCH];
__device__ float         g_m2p[NCLS * SCH * DCH];
__device__ float         g_binp[NCLS * SCH * DCH * 8];  // 7 bins used, pad 8
__device__ float         g_closs[NCLS];
__device__ int           g_ctick[NCLS];
__device__ int           g_gtick;

typedef unsigned long long ull;

__device__ __forceinline__ float ex2f(float x) {
    float y; asm("ex2.approx.ftz.f32 %0, %1;" : "=f"(y) : "f"(x)); return y;
}
__device__ __forceinline__ ull pk2(float lo, float hi) {
    ull r; asm("mov.b64 %0, {%1, %2};" : "=l"(r) : "f"(lo), "f"(hi)); return r;
}
__device__ __forceinline__ ull pkb(unsigned lo, unsigned hi) {
    ull r; asm("mov.b64 %0, {%1, %2};" : "=l"(r) : "r"(lo), "r"(hi)); return r;
}
__device__ __forceinline__ void upk2(float& lo, float& hi, ull v) {
    asm("mov.b64 {%0, %1}, %2;" : "=f"(lo), "=f"(hi) : "l"(v));
}
__device__ __forceinline__ ull fma2(ull a, ull b, ull c) {
    ull d; asm("fma.rn.f32x2 %0, %1, %2, %3;" : "=l"(d) : "l"(a), "l"(b), "l"(c)); return d;
}
__device__ __forceinline__ ull mul2(ull a, ull b) {
    ull d; asm("mul.rn.f32x2 %0, %1, %2;" : "=l"(d) : "l"(a), "l"(b)); return d;
}

// recurrence constants (exponent -12.5(k-t)^2 in base 2):
#define CLK  (-18.033688011112042f)    // -12.5*log2(e)
#define RA   (-36.06737602222409f)     // -25*log2(e)
#define RB   (90.16844005556021f)      //  62.5*log2(e)
#define CCM  (1.3887943864964021e-11f) // exp(-25)

// ───── K0: prep = feature transpose (blocks 0..255) + label counts (256..319)
__global__ __launch_bounds__(256) void prep_kernel(const float* __restrict__ feat,
                                                   const int* __restrict__ label) {
    __shared__ float sm[64][65];
    const int bi = blockIdx.x, tid = threadIdx.x;
    if (bi < 256) {
        const int pixbase = bi * 64;
        const int sub = tid >> 6, low = tid & 63;
#pragma unroll
        for (int it = 0; it < 16; it++) {
            int d = sub + it * 4;
            sm[d][low] = feat[d * FPX + pixbase + low];
        }
        __syncthreads();
#pragma unroll
        for (int it = 0; it < 16; it++) {
            int p_off = sub + it * 4;
            g_ft[(pixbase + p_off) * 64 + low] = sm[low][p_off];
        }
    } else {
        const int fp = (bi - 256) * 256 + tid;
        const int r = fp >> 7, c = fp & 127;
        const int4* lp = reinterpret_cast<const int4*>(label + (r * 4) * LBL + c * 4);
        unsigned pk[4];
#pragma unroll
        for (int dr = 0; dr < 4; dr++) {
            int4 v = lp[dr * (LBL / 4)];
            pk[dr] = (unsigned)v.x | ((unsigned)v.y << 8) |
                     ((unsigned)v.z << 16) | ((unsigned)v.w << 24);
        }
#pragma unroll
        for (int cls = 0; cls < NCLS; cls++) {
            unsigned u = (unsigned)cls * 0x01010101u;
            int s = 0;
#pragma unroll
            for (int dr = 0; dr < 4; dr++)
                s = __dp4a((int)(__vcmpeq4(pk[dr], u) & 0x01010101u), 0x01010101, s);
            g_cnt8[cls * FPX + fp] = (unsigned char)s;
        }
    }
}

// ───── K1: ordered compaction (one block per class)
__global__ __launch_bounds__(NTP) void compact_kernel() {
    const int cls = blockIdx.x;
    const int tid = threadIdx.x, lane = tid & 31, wid = tid >> 5;
    __shared__ unsigned sbuf[CHPX];
    __shared__ unsigned wtot[8], wbase[8];
    __shared__ int wsumw[8];
    __shared__ unsigned chtot_s;
    __shared__ int nacc_s;

    if (tid == 0) nacc_s = 0;
    unsigned gbase = 0;
    unsigned int* __restrict__ out = g_pairs + cls * FPX;

    for (int h = 0; h < FPX / CHPX; h++) {
        const int pxbase = h * CHPX + tid * 32;
        unsigned d[8];
        const uint4* src = reinterpret_cast<const uint4*>(g_cnt8 + cls * FPX + h * CHPX)
                           + tid * 2;
        uint4 v0 = src[0], v1 = src[1];
        d[0]=v0.x; d[1]=v0.y; d[2]=v0.z; d[3]=v0.w;
        d[4]=v1.x; d[5]=v1.y; d[6]=v1.z; d[7]=v1.w;

        int nnz = 0, ws = 0;
#pragma unroll
        for (int j = 0; j < 8; j++) {
            unsigned u = d[j];
            nnz += __popc(__vcmpne4(u, 0u) & 0x01010101u);
            ws  += __dp4a((int)u, 0x01010101, 0);
        }
        unsigned inc = (unsigned)nnz;
#pragma unroll
        for (int o = 1; o < 32; o <<= 1) {
            unsigned t = __shfl_up_sync(0xffffffffu, inc, o);
            if (lane >= o) inc += t;
        }
        if (lane == 31) wtot[wid] = inc;
        int wsr = ws;
#pragma unroll
        for (int o = 16; o; o >>= 1) wsr += __shfl_xor_sync(0xffffffffu, wsr, o);
        if (lane == 0) wsumw[wid] = wsr;
        __syncthreads();
        if (tid == 0) {
            unsigned run = 0; int ns = 0;
#pragma unroll
            for (int j = 0; j < 8; j++) { wbase[j] = run; run += wtot[j]; ns += wsumw[j]; }
            chtot_s = run;
            nacc_s += ns;
        }
        __syncthreads();

        unsigned rank = wbase[wid] + inc - (unsigned)nnz;
#pragma unroll
        for (int j = 0; j < 8; j++) {
            unsigned u = d[j];
#pragma unroll
            for (int b = 0; b < 4; b++) {
                unsigned w = (u >> (8 * b)) & 0xffu;
                if (w) sbuf[rank++] = (w << 16) | (unsigned)(pxbase + j * 4 + b);
            }
        }
        __syncthreads();
        unsigned chtot = chtot_s;
        for (unsigned j = tid; j < chtot; j += NTP) out[gbase + j] = sbuf[j];
        gbase += chtot;
        __syncthreads();
    }
    unsigned pl = (gbase + PADQ - 1) / PADQ * PADQ;
    for (unsigned k = gbase + tid; k < pl; k += NTP) out[k] = 0u;
    if (tid == 0) { g_len[cls] = (int)pl; g_n[cls] = (float)nacc_s; }
}

// ───── K2: partial moments per (class, chunk). lane = channel-pair.
__global__ __launch_bounds__(256) void mom_kernel() {
    const int cls = blockIdx.x, s = blockIdx.y;
    if (g_n[cls] < 1000.0f) return;
    const int tid = threadIdx.x, lane = tid & 31, wid = tid >> 5;
    const int len = g_len[cls];
    const unsigned* __restrict__ pr = g_pairs + cls * FPX;
    const float2* __restrict__ ft2 = reinterpret_cast<const float2*>(g_ft);

    ull s1 = 0ull, s2 = 0ull;
    for (int e = s + SCH * wid; e < len; e += SCH * 16) {
        unsigned pa = __ldg(pr + e);
        unsigned pb = __ldg(pr + e + SCH * 8);
        float2 fa = ft2[(pa & 0xFFFFu) * 32 + lane];
        float2 fc = ft2[(pb & 0xFFFFu) * 32 + lane];
        float wa = (float)(pa >> 16), wb = (float)(pb >> 16);
        ull fa2 = pk2(fa.x, fa.y), fc2 = pk2(fc.x, fc.y);
        ull wa2 = pk2(wa, wa),     wb2 = pk2(wb, wb);
        s1 = fma2(fa2, wa2, s1);
        s2 = fma2(mul2(fa2, fa2), wa2, s2);
        s1 = fma2(fc2, wb2, s1);
        s2 = fma2(mul2(fc2, fc2), wb2, s2);
    }
    __shared__ float2 sm1[8][32], sm2[8][32];
    float l1, h1, l2, h2;
    upk2(l1, h1, s1); upk2(l2, h2, s2);
    sm1[wid][lane] = make_float2(l1, h1);
    sm2[wid][lane] = make_float2(l2, h2);
    __syncthreads();
    if (tid < 32) {
        float a = 0.f, b = 0.f, c = 0.f, d = 0.f;
#pragma unroll
        for (int w = 0; w < 8; w++) {
            a += sm1[w][tid].x; b += sm1[w][tid].y;
            c += sm2[w][tid].x; d += sm2[w][tid].y;
        }
        int base = (cls * SCH + s) * DCH + tid * 2;
        g_m1p[base] = a; g_m1p[base + 1] = b;
        g_m2p[base] = c; g_m2p[base + 1] = d;
    }
}

__device__ __forceinline__ void kde_ch(unsigned pv, float2 fv, ull invs2, ull nmu2,
                                       ull cc2, ull* accP, ull* accN) {
    float wf = (float)(pv >> 16);
    ull f2 = pk2(fv.x, fv.y);
    ull t2 = fma2(f2, invs2, nmu2);
    float t0, t1; upk2(t0, t1, t2);
    float a0 = fabsf(t0), a1 = fabsf(t1);
    float x0 = 3.0f - a0, x1 = 3.0f - a1;
    float gl = ex2f(fmaf(CLK * x0, x0, 100.0f));
    float gh = ex2f(fmaf(CLK * x1, x1, 100.0f));
    float rl = ex2f(fmaf(RA, a0, RB));
    float rh = ex2f(fmaf(RA, a1, RB));
    unsigned m0 = (unsigned)(__float_as_int(t0) >> 31);
    unsigned m1 = (unsigned)(__float_as_int(t1) >> 31);
    unsigned wb = __float_as_uint(wf);
    ull wp2 = pkb(wb & ~m0, wb & ~m1);
    ull wn2 = pkb(wb &  m0, wb &  m1);
    ull g = pk2(gl, gh), r = pk2(rl, rh);
#pragma unroll
    for (int k = 0; k < 7; k++) {
        accP[k] = fma2(wp2, g, accP[k]);
        accN[k] = fma2(wn2, g, accN[k]);
        if (k < 6) { g = mul2(g, r); r = mul2(r, cc2); }
    }
}

// ───── K3: recurrence KDE per (class, chunk); class ticket -> bins+loss;
//          global ticket -> scalar.
__global__ __launch_bounds__(256) void kde_kernel(float* __restrict__ outp) {
    const int cls = blockIdx.x, sb = blockIdx.y;
    const int tid = threadIdx.x, lane = tid & 31, wid = tid >> 5;
    const float n = g_n[cls];
    const bool active = (n >= 1000.0f);

    __shared__ float sinv[DCH], snmu[DCH];
    __shared__ float2 stgP[8][32][7], stgN[8][32][7];
    __shared__ float red[8];
    __shared__ int sflag, gflag;

    if (active) {
        if (tid < DCH) {
            float S1 = 0.f, S2 = 0.f;
#pragma unroll
            for (int s = 0; s < SCH; s++) {
                int base = (cls * SCH + s) * DCH + tid;
                S1 += g_m1p[base];
                S2 += g_m2p[base];
            }
            float nsafe = fmaxf(n, 1.0f);
            float miu = S1 / nsafe;
            float var = fmaxf(S2 / nsafe - miu * miu, 0.0f) + 1e-10f;
            float invs = rsqrtf(var);
            sinv[tid] = invs;
            snmu[tid] = -miu * invs;
        }
    }
    __syncthreads();

    if (active) {
        const int len = g_len[cls];
        const unsigned* __restrict__ pr = g_pairs + cls * FPX;
        const float2* __restrict__ ft2 = reinterpret_cast<const float2*>(g_ft);
        const ull invs2 = pk2(sinv[2 * lane], sinv[2 * lane + 1]);
        const ull nmu2  = pk2(snmu[2 * lane], snmu[2 * lane + 1]);
        const ull cc2   = pk2(CCM, CCM);
        ull accP[7], accN[7];
#pragma unroll
        for (int k = 0; k < 7; k++) { accP[k] = 0ull; accN[k] = 0ull; }

        for (int e = sb + SCH * wid; e < len; e += SCH * 16) {
            unsigned pa = __ldg(pr + e);
            unsigned pb = __ldg(pr + e + SCH * 8);
            float2 fa = ft2[(pa & 0xFFFFu) * 32 + lane];
            float2 fc = ft2[(pb & 0xFFFFu) * 32 + lane];
            kde_ch(pa, fa, invs2, nmu2, cc2, accP, accN);
            kde_ch(pb, fc, invs2, nmu2, cc2, accP, accN);
        }
#pragma unroll
        for (int k = 0; k < 7; k++) {
            float lo, hi;
            upk2(lo, hi, accP[k]); stgP[wid][lane][k] = make_float2(lo, hi);
            upk2(lo, hi, accN[k]); stgN[wid][lane][k] = make_float2(lo, hi);
        }
    }
    __syncthreads();

    if (active && tid < DCH) {
        const int pi = tid >> 1, comp = tid & 1;
        float P[7], N[7];
#pragma unroll
        for (int k = 0; k < 7; k++) {
            float vP = 0.f, vN = 0.f;
#pragma unroll
            for (int w = 0; w < 8; w++) {
                float2 p2 = stgP[w][pi][k], n2 = stgN[w][pi][k];
                vP += comp ? p2.y : p2.x;
                vN += comp ? n2.y : n2.x;
            }
            P[k] = vP; N[k] = vN;
        }
        int base = ((cls * SCH + sb) * DCH + tid) * 8;
#pragma unroll
        for (int ib = 0; ib < 7; ib++)
            g_binp[base + ib] = P[6 - ib] + N[ib];   // fold sign banks
    }
    __threadfence();
    if (tid == 0) {
        int t = atomicAdd(&g_ctick[cls], 1);
        sflag = (t == SCH - 1) ? 1 : 0;
    }
    __syncthreads();

    if (sflag) {
        __threadfence();
        float myloss = 0.f;
        if (active && tid < DCH) {
            float sbin[7], tot = 0.f;
#pragma unroll
            for (int ib = 0; ib < 7; ib++) {
                float v = 0.f;
                for (int s = 0; s < SCH; s++)
                    v += g_binp[((cls * SCH + s) * DCH + tid) * 8 + ib];
                sbin[ib] = v; tot += v;
            }
            float inv = 1.0f / fmaxf(tot, 1e-30f);
            const float targ[7] = {0.00443305f, 0.05400558f, 0.24203623f, 0.39905027f,
                                   0.24203623f, 0.05400558f, 0.00443305f};
            float L = 0.f;
#pragma unroll
            for (int ib = 0; ib < 7; ib++) {
                float dif = fabsf(sbin[ib] * inv - targ[ib]);
                L += (dif < 1.0f) ? 0.5f * dif * dif : (dif - 0.5f);
            }
            myloss = L;
        }
        float v = myloss;
#pragma unroll
        for (int o = 16; o; o >>= 1) v += __shfl_xor_sync(0xffffffffu, v, o);
        if (lane == 0) red[wid] = v;
        __syncthreads();
        if (tid == 0) {
            float sum = 0.f;
#pragma unroll
            for (int w = 0; w < 8; w++) sum += red[w];
            g_closs[cls] = active ? sum * (1.0f / (7.0f * (float)DCH)) : 0.f;
            g_ctick[cls] = 0;   // reset for next graph replay
            __threadfence();
            int gt = atomicAdd(&g_gtick, 1);
            gflag = (gt == NCLS - 1) ? 1 : 0;
        }
        __syncthreads();
        if (gflag && tid == 0) {
            __threadfence();
            float num = 0.f, den = 0.f;
#pragma unroll
            for (int c = 0; c < NCLS; c++) {
                num += g_closs[c];
                den += (g_n[c] >= 1000.0f) ? 1.0f : 0.0f;
            }
            outp[0] = num / den;
            g_gtick = 0;        // reset for next graph replay
        }
    }
}

extern "C" void kernel_launch(void* const* d_in, const int* in_sizes, int n_in,
                              void* d_out, int out_size) {
    const float* feature;
    const int*   label;
    if (in_sizes[0] == DCH * FPX) {
        feature = (const float*)d_in[0];
        label   = (const int*)d_in[1];
    } else {
        feature = (const float*)d_in[1];
        label   = (const int*)d_in[0];
    }
    prep_kernel<<<320, 256>>>(feature, label);
    compact_kernel<<<NCLS, NTP>>>();
    mom_kernel<<<dim3(NCLS, SCH), 256>>>();
    kde_kernel<<<dim3(NCLS, SCH), 256>>>((float*)d_out);
}

// round 11
// speedup vs baseline: 1.2537x; 1.0985x over previous
#include <cuda_runtime.h>

#define NCLS 19
#define FPX  16384      // 128*128 feature pixels
#define DCH  64
#define LBL  512
#define SCH  64         // list chunks (grid.y of mom/kde)
#define NTP  256
#define PADQ (SCH*16)   // 1024: stream tiling quantum for mom+kde
#define CHPX 8192

__device__ unsigned char g_cnt8[NCLS * FPX];
__device__ unsigned int  g_pairs[NCLS * FPX];   // (w<<16)|pixel, zero-padded
__device__ int           g_len[NCLS];
__device__ float         g_n[NCLS];
__device__ float         g_ft[FPX * DCH];       // transposed feature [p][d]
__device__ float         g_m1p[NCLS * SCH * DCH];
__device__ float         g_m2p[NCLS * SCH * DCH];
__device__ float         g_binp[NCLS * SCH * DCH * 8];  // 7 bins used, pad 8
__device__ float         g_closs[NCLS];
__device__ int           g_ctick[NCLS];
__device__ int           g_gtick;

typedef unsigned long long ull;

__device__ __forceinline__ float ex2f(float x) {
    float y; asm("ex2.approx.ftz.f32 %0, %1;" : "=f"(y) : "f"(x)); return y;
}
__device__ __forceinline__ ull pk2(float lo, float hi) {
    ull r; asm("mov.b64 %0, {%1, %2};" : "=l"(r) : "f"(lo), "f"(hi)); return r;
}
__device__ __forceinline__ ull pkb(unsigned lo, unsigned hi) {
    ull r; asm("mov.b64 %0, {%1, %2};" : "=l"(r) : "r"(lo), "r"(hi)); return r;
}
__device__ __forceinline__ void upk2(float& lo, float& hi, ull v) {
    asm("mov.b64 {%0, %1}, %2;" : "=f"(lo), "=f"(hi) : "l"(v));
}
__device__ __forceinline__ ull fma2(ull a, ull b, ull c) {
    ull d; asm("fma.rn.f32x2 %0, %1, %2, %3;" : "=l"(d) : "l"(a), "l"(b), "l"(c)); return d;
}
__device__ __forceinline__ ull mul2(ull a, ull b) {
    ull d; asm("mul.rn.f32x2 %0, %1, %2;" : "=l"(d) : "l"(a), "l"(b)); return d;
}

// recurrence constants (exponent -12.5(k-t)^2 in base 2):
#define CLK  (-18.033688011112042f)    // -12.5*log2(e)
#define RA   (-36.06737602222409f)     // -25*log2(e)
#define RB   (90.16844005556021f)      //  62.5*log2(e)
#define CCM  (1.3887943864964021e-11f) // exp(-25)

// ───── K0: prep = feature transpose (blocks 0..255) + label counts (256..319)
__global__ __launch_bounds__(256) void prep_kernel(const float* __restrict__ feat,
                                                   const int* __restrict__ label) {
    __shared__ float sm[64][65];
    const int bi = blockIdx.x, tid = threadIdx.x;
    if (bi < 256) {
        const int pixbase = bi * 64;
        const int sub = tid >> 6, low = tid & 63;
#pragma unroll
        for (int it = 0; it < 16; it++) {
            int d = sub + it * 4;
            sm[d][low] = feat[d * FPX + pixbase + low];
        }
        __syncthreads();
#pragma unroll
        for (int it = 0; it < 16; it++) {
            int p_off = sub + it * 4;
            g_ft[(pixbase + p_off) * 64 + low] = sm[low][p_off];
        }
    } else {
        const int fp = (bi - 256) * 256 + tid;
        const int r = fp >> 7, c = fp & 127;
        const int4* lp = reinterpret_cast<const int4*>(label + (r * 4) * LBL + c * 4);
        unsigned pk[4];
#pragma unroll
        for (int dr = 0; dr < 4; dr++) {
            int4 v = lp[dr * (LBL / 4)];
            pk[dr] = (unsigned)v.x | ((unsigned)v.y << 8) |
                     ((unsigned)v.z << 16) | ((unsigned)v.w << 24);
        }
#pragma unroll
        for (int cls = 0; cls < NCLS; cls++) {
            unsigned u = (unsigned)cls * 0x01010101u;
            int s = 0;
#pragma unroll
            for (int dr = 0; dr < 4; dr++)
                s = __dp4a((int)(__vcmpeq4(pk[dr], u) & 0x01010101u), 0x01010101, s);
            g_cnt8[cls * FPX + fp] = (unsigned char)s;
        }
    }
}

// ───── K1: ordered compaction (one block per class)
__global__ __launch_bounds__(NTP) void compact_kernel() {
    const int cls = blockIdx.x;
    const int tid = threadIdx.x, lane = tid & 31, wid = tid >> 5;
    __shared__ unsigned sbuf[CHPX];
    __shared__ unsigned wtot[8], wbase[8];
    __shared__ int wsumw[8];
    __shared__ unsigned chtot_s;
    __shared__ int nacc_s;

    if (tid == 0) nacc_s = 0;
    unsigned gbase = 0;
    unsigned int* __restrict__ out = g_pairs + cls * FPX;

    for (int h = 0; h < FPX / CHPX; h++) {
        const int pxbase = h * CHPX + tid * 32;
        unsigned d[8];
        const uint4* src = reinterpret_cast<const uint4*>(g_cnt8 + cls * FPX + h * CHPX)
                           + tid * 2;
        uint4 v0 = src[0], v1 = src[1];
        d[0]=v0.x; d[1]=v0.y; d[2]=v0.z; d[3]=v0.w;
        d[4]=v1.x; d[5]=v1.y; d[6]=v1.z; d[7]=v1.w;

        int nnz = 0, ws = 0;
#pragma unroll
        for (int j = 0; j < 8; j++) {
            unsigned u = d[j];
            nnz += __popc(__vcmpne4(u, 0u) & 0x01010101u);
            ws  += __dp4a((int)u, 0x01010101, 0);
        }
        unsigned inc = (unsigned)nnz;
#pragma unroll
        for (int o = 1; o < 32; o <<= 1) {
            unsigned t = __shfl_up_sync(0xffffffffu, inc, o);
            if (lane >= o) inc += t;
        }
        if (lane == 31) wtot[wid] = inc;
        int wsr = ws;
#pragma unroll
        for (int o = 16; o; o >>= 1) wsr += __shfl_xor_sync(0xffffffffu, wsr, o);
        if (lane == 0) wsumw[wid] = wsr;
        __syncthreads();
        if (tid == 0) {
            unsigned run = 0; int ns = 0;
#pragma unroll
            for (int j = 0; j < 8; j++) { wbase[j] = run; run += wtot[j]; ns += wsumw[j]; }
            chtot_s = run;
            nacc_s += ns;
        }
        __syncthreads();

        unsigned rank = wbase[wid] + inc - (unsigned)nnz;
#pragma unroll
        for (int j = 0; j < 8; j++) {
            unsigned u = d[j];
#pragma unroll
            for (int b = 0; b < 4; b++) {
                unsigned w = (u >> (8 * b)) & 0xffu;
                if (w) sbuf[rank++] = (w << 16) | (unsigned)(pxbase + j * 4 + b);
            }
        }
        __syncthreads();
        unsigned chtot = chtot_s;
        for (unsigned j = tid; j < chtot; j += NTP) out[gbase + j] = sbuf[j];
        gbase += chtot;
        __syncthreads();
    }
    unsigned pl = (gbase + PADQ - 1) / PADQ * PADQ;
    for (unsigned k = gbase + tid; k < pl; k += NTP) out[k] = 0u;
    if (tid == 0) { g_len[cls] = (int)pl; g_n[cls] = (float)nacc_s; }
}

// ───── K2: partial moments per (class, chunk). lane = channel-pair.
__global__ __launch_bounds__(256) void mom_kernel() {
    const int cls = blockIdx.x, s = blockIdx.y;
    if (g_n[cls] < 1000.0f) return;
    const int tid = threadIdx.x, lane = tid & 31, wid = tid >> 5;
    const int len = g_len[cls];
    const unsigned* __restrict__ pr = g_pairs + cls * FPX;
    const float2* __restrict__ ft2 = reinterpret_cast<const float2*>(g_ft);

    ull s1 = 0ull, s2 = 0ull;
    for (int e = s + SCH * wid; e < len; e += SCH * 16) {
        unsigned pa = __ldg(pr + e);
        unsigned pb = __ldg(pr + e + SCH * 8);
        float2 fa = ft2[(pa & 0xFFFFu) * 32 + lane];
        float2 fc = ft2[(pb & 0xFFFFu) * 32 + lane];
        float wa = (float)(pa >> 16), wb = (float)(pb >> 16);
        ull fa2 = pk2(fa.x, fa.y), fc2 = pk2(fc.x, fc.y);
        ull wa2 = pk2(wa, wa),     wb2 = pk2(wb, wb);
        s1 = fma2(fa2, wa2, s1);
        s2 = fma2(mul2(fa2, fa2), wa2, s2);
        s1 = fma2(fc2, wb2, s1);
        s2 = fma2(mul2(fc2, fc2), wb2, s2);
    }
    __shared__ float2 sm1[8][32], sm2[8][32];
    float l1, h1, l2, h2;
    upk2(l1, h1, s1); upk2(l2, h2, s2);
    sm1[wid][lane] = make_float2(l1, h1);
    sm2[wid][lane] = make_float2(l2, h2);
    __syncthreads();
    if (tid < 32) {
        float a = 0.f, b = 0.f, c = 0.f, d = 0.f;
#pragma unroll
        for (int w = 0; w < 8; w++) {
            a += sm1[w][tid].x; b += sm1[w][tid].y;
            c += sm2[w][tid].x; d += sm2[w][tid].y;
        }
        int base = (cls * SCH + s) * DCH + tid * 2;
        g_m1p[base] = a; g_m1p[base + 1] = b;
        g_m2p[base] = c; g_m2p[base + 1] = d;
    }
}

// ───── K3: recurrence KDE, 4 independent entry-chains per warp-iteration.
__global__ __launch_bounds__(128, 6) void kde_kernel(float* __restrict__ outp) {
    const int cls = blockIdx.x, sb = blockIdx.y;
    const int tid = threadIdx.x, lane = tid & 31, wid = tid >> 5;
    const float n = g_n[cls];
    const bool active = (n >= 1000.0f);

    __shared__ float sinv[DCH], snmu[DCH];
    __shared__ float2 stgP[4][32][7], stgN[4][32][7];
    __shared__ float red[4];
    __shared__ int sflag, gflag;

    if (active && tid < DCH) {
        float S1 = 0.f, S2 = 0.f;
#pragma unroll
        for (int s = 0; s < SCH; s++) {
            int base = (cls * SCH + s) * DCH + tid;
            S1 += g_m1p[base];
            S2 += g_m2p[base];
        }
        float nsafe = fmaxf(n, 1.0f);
        float miu = S1 / nsafe;
        float var = fmaxf(S2 / nsafe - miu * miu, 0.0f) + 1e-10f;
        float invs = rsqrtf(var);
        sinv[tid] = invs;
        snmu[tid] = -miu * invs;
    }
    __syncthreads();

    if (active) {
        const int len = g_len[cls];
        const unsigned* __restrict__ pr = g_pairs + cls * FPX;
        const float2* __restrict__ ft2 = reinterpret_cast<const float2*>(g_ft);
        const ull invs2 = pk2(sinv[2 * lane], sinv[2 * lane + 1]);
        const ull nmu2  = pk2(snmu[2 * lane], snmu[2 * lane + 1]);
        const ull cc2   = pk2(CCM, CCM);
        ull accP[7], accN[7];
#pragma unroll
        for (int k = 0; k < 7; k++) { accP[k] = 0ull; accN[k] = 0ull; }

        for (int e0 = sb + SCH * 4 * wid; e0 < len; e0 += SCH * 16) {
            ull g[4], r[4], wp[4], wn[4];
#pragma unroll
            for (int j = 0; j < 4; j++) {
                unsigned pv = __ldg(pr + e0 + SCH * j);
                float2 fv = ft2[(pv & 0xFFFFu) * 32 + lane];
                float wf = (float)(pv >> 16);
                ull t2 = fma2(pk2(fv.x, fv.y), invs2, nmu2);
                float t0, t1; upk2(t0, t1, t2);
                float a0 = fabsf(t0), a1 = fabsf(t1);
                float x0 = 3.0f - a0, x1 = 3.0f - a1;
                float gl = ex2f(fmaf(CLK * x0, x0, 100.0f));
                float gh = ex2f(fmaf(CLK * x1, x1, 100.0f));
                float rl = ex2f(fmaf(RA, a0, RB));
                float rh = ex2f(fmaf(RA, a1, RB));
                unsigned m0 = (unsigned)(__float_as_int(t0) >> 31);
                unsigned m1 = (unsigned)(__float_as_int(t1) >> 31);
                unsigned wb = __float_as_uint(wf);
                wp[j] = pkb(wb & ~m0, wb & ~m1);
                wn[j] = pkb(wb &  m0, wb &  m1);
                g[j] = pk2(gl, gh);
                r[j] = pk2(rl, rh);
            }
#pragma unroll
            for (int s = 0; s < 7; s++) {
#pragma unroll
                for (int j = 0; j < 4; j++) {
                    accP[s] = fma2(wp[j], g[j], accP[s]);
                    accN[s] = fma2(wn[j], g[j], accN[s]);
                    if (s < 6) { g[j] = mul2(g[j], r[j]); r[j] = mul2(r[j], cc2); }
                }
            }
        }
#pragma unroll
        for (int k = 0; k < 7; k++) {
            float lo, hi;
            upk2(lo, hi, accP[k]); stgP[wid][lane][k] = make_float2(lo, hi);
            upk2(lo, hi, accN[k]); stgN[wid][lane][k] = make_float2(lo, hi);
        }
    }
    __syncthreads();

    if (active && tid < DCH) {
        const int pi = tid >> 1, comp = tid & 1;
        float P[7], N[7];
#pragma unroll
        for (int k = 0; k < 7; k++) {
            float vP = 0.f, vN = 0.f;
#pragma unroll
            for (int w = 0; w < 4; w++) {
                float2 p2 = stgP[w][pi][k], n2 = stgN[w][pi][k];
                vP += comp ? p2.y : p2.x;
                vN += comp ? n2.y : n2.x;
            }
            P[k] = vP; N[k] = vN;
        }
        int base = ((cls * SCH + sb) * DCH + tid) * 8;
#pragma unroll
        for (int ib = 0; ib < 7; ib++)
            g_binp[base + ib] = P[6 - ib] + N[ib];   // fold sign banks
    }
    __threadfence();
    if (tid == 0) {
        int t = atomicAdd(&g_ctick[cls], 1);
        sflag = (t == SCH - 1) ? 1 : 0;
    }
    __syncthreads();

    if (sflag) {
        __threadfence();
        float myloss = 0.f;
        if (active && tid < DCH) {
            float sbin[7] = {0.f, 0.f, 0.f, 0.f, 0.f, 0.f, 0.f};
            const float4* bp = reinterpret_cast<const float4*>(g_binp);
            for (int s = 0; s < SCH; s++) {
                int b4 = ((cls * SCH + s) * DCH + tid) * 2;
                float4 v0 = bp[b4], v1 = bp[b4 + 1];
                sbin[0] += v0.x; sbin[1] += v0.y; sbin[2] += v0.z; sbin[3] += v0.w;
                sbin[4] += v1.x; sbin[5] += v1.y; sbin[6] += v1.z;
            }
            float tot = 0.f;
#pragma unroll
            for (int ib = 0; ib < 7; ib++) tot += sbin[ib];
            float inv = 1.0f / fmaxf(tot, 1e-30f);
            const float targ[7] = {0.00443305f, 0.05400558f, 0.24203623f, 0.39905027f,
                                   0.24203623f, 0.05400558f, 0.00443305f};
            float L = 0.f;
#pragma unroll
            for (int ib = 0; ib < 7; ib++) {
                float dif = fabsf(sbin[ib] * inv - targ[ib]);
                L += (dif < 1.0f) ? 0.5f * dif * dif : (dif - 0.5f);
            }
            myloss = L;
        }
        float v = myloss;
#pragma unroll
        for (int o = 16; o; o >>= 1) v += __shfl_xor_sync(0xffffffffu, v, o);
        if (lane == 0) red[wid] = v;
        __syncthreads();
        if (tid == 0) {
            float sum = red[0] + red[1] + red[2] + red[3];
            g_closs[cls] = active ? sum * (1.0f / (7.0f * (float)DCH)) : 0.f;
            g_ctick[cls] = 0;   // reset for next graph replay
            __threadfence();
            int gt = atomicAdd(&g_gtick, 1);
            gflag = (gt == NCLS - 1) ? 1 : 0;
        }
        __syncthreads();
        if (gflag && tid == 0) {
            __threadfence();
            float num = 0.f, den = 0.f;
#pragma unroll
            for (int c = 0; c < NCLS; c++) {
                num += g_closs[c];
                den += (g_n[c] >= 1000.0f) ? 1.0f : 0.0f;
            }
            outp[0] = num / den;
            g_gtick = 0;        // reset for next graph replay
        }
    }
}

extern "C" void kernel_launch(void* const* d_in, const int* in_sizes, int n_in,
                              void* d_out, int out_size) {
    const float* feature;
    const int*   label;
    if (in_sizes[0] == DCH * FPX) {
        feature = (const float*)d_in[0];
        label   = (const int*)d_in[1];
    } else {
        feature = (const float*)d_in[1];
        label   = (const int*)d_in[0];
    }
    prep_kernel<<<320, 256>>>(feature, label);
    compact_kernel<<<NCLS, NTP>>>();
    mom_kernel<<<dim3(NCLS, SCH), 256>>>();
    kde_kernel<<<dim3(NCLS, SCH), 128>>>((float*)d_out);
}